// round 1
// baseline (speedup 1.0000x reference)
#include <cuda_runtime.h>
#include <math.h>

// ---------------------------------------------------------------------------
// RelationalPathGNN: 2-layer relational GNN with edge softmax.
// N=20000 nodes, E=160000 edges, EMB=64, HID=128, R=8 relations.
//
// Pipeline per launch (all recomputed -> deterministic, graph-capturable):
//   1. degrees + relation histogram (atomics)
//   2. tiny scan -> 64-aligned per-relation segment offsets
//   3. scatter edges into relation-grouped permutation
//   per layer:
//   4. fused gather + grouped GEMM  m[e] = [hn[src], ef[e], ne[dst]] @ W[eid[e]]
//   5. segment softmax over dst (max via ordered-uint atomicMax, sum via atomicAdd)
//   6. scatter-aggregate a*m into agg[dst] (float atomics)
//   7. epilogue: (agg + ne@L) * indeg^-1/2 + b, relu
// ---------------------------------------------------------------------------

namespace {
constexpr int N_   = 20000;
constexpr int E_   = 160000;
constexpr int EMB_ = 64;
constexpr int HID_ = 128;
constexpr int R_   = 8;
constexpr int TM   = 64;                       // edge-tile rows for grouped GEMM
constexpr int MTILES = (E_ + R_ * TM) / TM;    // 2508 worst-case tiles
}

// ------------------------- scratch (static device) -------------------------
__device__ float    g_m[(size_t)E_ * HID_];    // edge messages (reused L2: E*64)
__device__ float    g_h1[(size_t)N_ * HID_];   // layer-1 output
__device__ float    g_outdeg[N_];
__device__ float    g_indeg[N_];
__device__ float    g_inv_out[N_];
__device__ float    g_inv_in[N_];
__device__ int      g_cnt[R_];
__device__ int      g_off[R_ + 1];
__device__ int      g_cur[R_];
__device__ int      g_perm[E_ + R_ * TM];
__device__ float    g_zn[N_];
__device__ unsigned g_zmax[N_];
__device__ float    g_zbuf[E_];                // z, then reused as coef
__device__ float    g_ez[E_];
__device__ float    g_denom[N_];
__device__ float    g_agg[(size_t)N_ * HID_];

// ordered-uint encoding for float atomicMax (monotone over all finite floats)
__device__ __forceinline__ unsigned f2ord(float x) {
    unsigned u = __float_as_uint(x);
    return (u & 0x80000000u) ? ~u : (u | 0x80000000u);
}
__device__ __forceinline__ float ord2f(unsigned u) {
    return (u & 0x80000000u) ? __uint_as_float(u ^ 0x80000000u)
                             : __uint_as_float(~u);
}

// ------------------------------ prep kernels -------------------------------
__global__ void k_prep_zero() {
    int i = blockIdx.x * blockDim.x + threadIdx.x;
    if (i < N_) { g_outdeg[i] = 0.f; g_indeg[i] = 0.f; }
    if (i < R_) g_cnt[i] = 0;
}

__global__ void k_count(const int* __restrict__ src, const int* __restrict__ dst,
                        const int* __restrict__ eid) {
    int e = blockIdx.x * blockDim.x + threadIdx.x;
    if (e >= E_) return;
    atomicAdd(&g_outdeg[src[e]], 1.f);
    atomicAdd(&g_indeg[dst[e]], 1.f);
    atomicAdd(&g_cnt[eid[e]], 1);
}

__global__ void k_inv() {
    int i = blockIdx.x * blockDim.x + threadIdx.x;
    if (i >= N_) return;
    g_inv_out[i] = 1.f / sqrtf(fmaxf(g_outdeg[i], 1.f));
    g_inv_in[i]  = 1.f / sqrtf(fmaxf(g_indeg[i], 1.f));
}

__global__ void k_scan() {
    int o = 0;
    for (int r = 0; r < R_; r++) {
        g_off[r] = o;
        g_cur[r] = o;
        o += ((g_cnt[r] + TM - 1) / TM) * TM;   // 64-align each segment
    }
    g_off[R_] = o;
}

__global__ void k_scatter(const int* __restrict__ eid) {
    int e = blockIdx.x * blockDim.x + threadIdx.x;
    if (e >= E_) return;
    int pos = atomicAdd(&g_cur[eid[e]], 1);
    g_perm[pos] = e;
}

// --------------------------- per-layer zeroing -----------------------------
template <int NOUT>
__global__ void k_layer_zero() {
    int i = blockIdx.x * blockDim.x + threadIdx.x;
    if (i < N_ * NOUT) g_agg[i] = 0.f;
    if (i < N_) { g_zmax[i] = 0u; g_denom[i] = 0.f; }
}

// --------------------- fused gather + grouped GEMM -------------------------
// m[e, :] = concat(h[src[e]] * inv_out[src[e]], edge_feat[e], node_emb[dst[e]])
//           @ W[eid[e]]
// Rows are relation-grouped via g_perm; every 64-row tile is relation-uniform.
template <int FIN, int NOUT, bool H_FROM_H1>
__global__ void k_gemm(const float* __restrict__ hsrc_in,
                       const float* __restrict__ ef,
                       const float* __restrict__ ne,
                       const float* __restrict__ W,
                       const int* __restrict__ src,
                       const int* __restrict__ dst) {
    constexpr int K   = FIN + 2 * EMB_;
    constexpr int KT  = 16;
    constexpr int CPT = NOUT / 16;             // cols per thread (8 or 4)

    __shared__ float As[KT][TM + 4];
    __shared__ float Bs[KT][NOUT + 4];
    __shared__ int   s_e[TM];
    __shared__ int   s_src[TM];
    __shared__ int   s_dst[TM];
    __shared__ float s_sc[TM];

    const float* hsrc = H_FROM_H1 ? (const float*)g_h1 : hsrc_in;

    int tx = threadIdx.x, ty = threadIdx.y;
    int tid = ty * 16 + tx;
    int m0 = blockIdx.x * TM;
    if (m0 >= g_off[R_]) return;

    int rel = 0;
#pragma unroll
    for (int r = 1; r <= R_; r++)
        if (m0 >= g_off[r]) rel = r;
    int seg_end = g_off[rel] + g_cnt[rel];

    if (tid < TM) {
        int gi = m0 + tid;
        int e = (gi < seg_end) ? g_perm[gi] : -1;
        s_e[tid] = e;
        if (e >= 0) {
            int s = src[e];
            s_src[tid] = s;
            s_dst[tid] = dst[e];
            s_sc[tid]  = g_inv_out[s];
        }
    }
    __syncthreads();

    const float* Wr = W + (size_t)rel * K * NOUT;

    float acc[4][CPT];
#pragma unroll
    for (int i = 0; i < 4; i++)
#pragma unroll
        for (int j = 0; j < CPT; j++) acc[i][j] = 0.f;

    int am  = tid >> 2;           // row this thread gathers for A
    int ak0 = (tid & 3) * 4;      // first of 4 consecutive k's

    for (int kt = 0; kt < K / KT; kt++) {
        // ---- gather A tile (64 rows x 16 k's) ----
        {
            int kg = kt * KT + ak0;
            int e = s_e[am];
            float4 v = make_float4(0.f, 0.f, 0.f, 0.f);
            if (e >= 0) {
                if (kg < FIN) {
                    v = *(const float4*)(hsrc + (size_t)s_src[am] * FIN + kg);
                    float sc = s_sc[am];
                    v.x *= sc; v.y *= sc; v.z *= sc; v.w *= sc;
                } else if (kg < FIN + EMB_) {
                    v = *(const float4*)(ef + (size_t)e * EMB_ + (kg - FIN));
                } else {
                    v = *(const float4*)(ne + (size_t)s_dst[am] * EMB_ +
                                         (kg - FIN - EMB_));
                }
            }
            As[ak0 + 0][am] = v.x;
            As[ak0 + 1][am] = v.y;
            As[ak0 + 2][am] = v.z;
            As[ak0 + 3][am] = v.w;
        }
        // ---- load B tile (16 x NOUT) ----
#pragma unroll
        for (int c = 0; c < CPT / 4; c++) {
            int l   = (c * 256 + tid) * 4;
            int kk  = l / NOUT;
            int col = l % NOUT;
            float4 v = *(const float4*)(Wr + (size_t)(kt * KT + kk) * NOUT + col);
            *(float4*)&Bs[kk][col] = v;
        }
        __syncthreads();

#pragma unroll
        for (int kk = 0; kk < KT; kk++) {
            float4 a4 = *(const float4*)&As[kk][ty * 4];
            float av[4] = {a4.x, a4.y, a4.z, a4.w};
            float bv[CPT];
#pragma unroll
            for (int c = 0; c < CPT / 4; c++) {
                float4 b4 = *(const float4*)&Bs[kk][tx * CPT + c * 4];
                bv[c * 4 + 0] = b4.x;
                bv[c * 4 + 1] = b4.y;
                bv[c * 4 + 2] = b4.z;
                bv[c * 4 + 3] = b4.w;
            }
#pragma unroll
            for (int i = 0; i < 4; i++)
#pragma unroll
                for (int j = 0; j < CPT; j++)
                    acc[i][j] += av[i] * bv[j];
        }
        __syncthreads();
    }

    // ---- scatter-store m rows ----
#pragma unroll
    for (int i = 0; i < 4; i++) {
        int m = ty * 4 + i;
        int e = s_e[m];
        if (e >= 0) {
            float* dp = g_m + (size_t)e * NOUT + tx * CPT;
#pragma unroll
            for (int c = 0; c < CPT / 4; c++) {
                float4 v = make_float4(acc[i][c * 4 + 0], acc[i][c * 4 + 1],
                                       acc[i][c * 4 + 2], acc[i][c * 4 + 3]);
                *(float4*)(dp + c * 4) = v;
            }
        }
    }
}

// ----------------------------- attention path ------------------------------
// zn[n] = node_emb[n] . A[0:64]   (warp per node)
__global__ void k_zn(const float* __restrict__ ne, const float* __restrict__ A) {
    int gt = blockIdx.x * blockDim.x + threadIdx.x;
    int w = gt >> 5, lane = gt & 31;
    if (w >= N_) return;
    float s = ne[(size_t)w * 64 + lane] * A[lane] +
              ne[(size_t)w * 64 + 32 + lane] * A[32 + lane];
#pragma unroll
    for (int o = 16; o; o >>= 1) s += __shfl_xor_sync(0xffffffffu, s, o);
    if (lane == 0) g_zn[w] = s;
}

// z[e] = leaky_relu(zn[dst] + m[e] . A[EMB:]) ; atomicMax per-dst
template <int NOUT>
__global__ void k_logits(const float* __restrict__ At, const int* __restrict__ dst) {
    int gt = blockIdx.x * blockDim.x + threadIdx.x;
    int e = gt >> 5, lane = gt & 31;
    if (e >= E_) return;
    float s = 0.f;
#pragma unroll
    for (int c = 0; c < NOUT / 32; c++)
        s += g_m[(size_t)e * NOUT + c * 32 + lane] * At[c * 32 + lane];
#pragma unroll
    for (int o = 16; o; o >>= 1) s += __shfl_xor_sync(0xffffffffu, s, o);
    if (lane == 0) {
        int d = dst[e];
        float z = g_zn[d] + s;
        z = (z > 0.f) ? z : 0.01f * z;   // leaky_relu, slope 0.01
        g_zbuf[e] = z;
        atomicMax(&g_zmax[d], f2ord(z));
    }
}

__global__ void k_exp(const int* __restrict__ dst) {
    int e = blockIdx.x * blockDim.x + threadIdx.x;
    if (e >= E_) return;
    int d = dst[e];
    float ez = expf(g_zbuf[e] - ord2f(g_zmax[d]));
    g_ez[e] = ez;
    atomicAdd(&g_denom[d], ez);
}

__global__ void k_coef(const int* __restrict__ dst) {
    int e = blockIdx.x * blockDim.x + threadIdx.x;
    if (e >= E_) return;
    g_zbuf[e] = g_ez[e] / g_denom[dst[e]];
}

// agg[dst] += coef * m[e]   (one thread per (e, j))
template <int NOUT>
__global__ void k_agg(const int* __restrict__ dst) {
    int idx = blockIdx.x * blockDim.x + threadIdx.x;
    int e = idx / NOUT;
    int j = idx - e * NOUT;
    if (e >= E_) return;
    float v = g_zbuf[e] * g_m[idx];
    atomicAdd(&g_agg[(size_t)dst[e] * NOUT + j], v);
}

// out[n] = relu((agg[n] + ne[n] @ L) * inv_in[n] + b)
template <int NOUT, bool TO_H1>
__global__ void k_final(const float* __restrict__ ne, const float* __restrict__ L,
                        const float* __restrict__ b, float* __restrict__ out) {
    constexpr int Y = 256 / NOUT;   // nodes per compute pass
    __shared__ float sL[64 * NOUT];
    __shared__ float sne[Y][64];
    int tid = threadIdx.x;
    for (int i = tid; i < 64 * NOUT; i += 256) sL[i] = L[i];
    int n0 = blockIdx.x * 16;
    int ty = tid / NOUT, j = tid % NOUT;

    for (int it = 0; it < 16 / Y; it++) {
        __syncthreads();
        if (tid < Y * 64) {
            int nn = n0 + it * Y + tid / 64;
            sne[tid / 64][tid & 63] =
                (nn < N_) ? ne[(size_t)nn * 64 + (tid & 63)] : 0.f;
        }
        __syncthreads();
        int n = n0 + it * Y + ty;
        if (n < N_) {
            float acc = 0.f;
#pragma unroll
            for (int k = 0; k < 64; k++) acc += sne[ty][k] * sL[k * NOUT + j];
            float v = (g_agg[(size_t)n * NOUT + j] + acc) * g_inv_in[n] + b[j];
            v = fmaxf(v, 0.f);
            if (TO_H1) g_h1[(size_t)n * NOUT + j] = v;
            else       out[(size_t)n * NOUT + j] = v;
        }
    }
}

// ------------------------------- launcher ----------------------------------
extern "C" void kernel_launch(void* const* d_in, const int* in_sizes, int n_in,
                              void* d_out, int out_size) {
    const float* node_emb  = (const float*)d_in[0];
    const float* edge_feat = (const float*)d_in[1];
    const float* W1        = (const float*)d_in[2];
    const float* A1        = (const float*)d_in[3];
    const float* b1        = (const float*)d_in[4];
    const float* L1        = (const float*)d_in[5];
    const float* W2        = (const float*)d_in[6];
    const float* A2        = (const float*)d_in[7];
    const float* b2        = (const float*)d_in[8];
    const float* L2        = (const float*)d_in[9];
    const int*   eid       = (const int*)d_in[10];
    const int*   src       = (const int*)d_in[11];
    const int*   dst       = (const int*)d_in[12];
    float*       out       = (float*)d_out;
    (void)in_sizes; (void)n_in; (void)out_size;

    const int gN = (N_ + 255) / 256;
    const int gE = (E_ + 255) / 256;

    // prep (recomputed each launch: deterministic, capture-safe)
    k_prep_zero<<<gN, 256>>>();
    k_count<<<gE, 256>>>(src, dst, eid);
    k_inv<<<gN, 256>>>();
    k_scan<<<1, 1>>>();
    k_scatter<<<gE, 256>>>(eid);

    // ---- layer 1: FIN=64, K=192, NOUT=128 ----
    k_layer_zero<HID_><<<(N_ * HID_ + 255) / 256, 256>>>();
    k_gemm<EMB_, HID_, false><<<MTILES, dim3(16, 16)>>>(
        node_emb, edge_feat, node_emb, W1, src, dst);
    k_zn<<<(N_ + 3) / 4, 128>>>(node_emb, A1);
    k_logits<HID_><<<(E_ + 3) / 4, 128>>>(A1 + EMB_, dst);
    k_exp<<<gE, 256>>>(dst);
    k_coef<<<gE, 256>>>(dst);
    k_agg<HID_><<<(E_ * HID_) / 256, 256>>>(dst);
    k_final<HID_, true><<<(N_ + 15) / 16, 256>>>(node_emb, L1, b1, nullptr);

    // ---- layer 2: FIN=128, K=256, NOUT=64 ----
    k_layer_zero<EMB_><<<(N_ * EMB_ + 255) / 256, 256>>>();
    k_gemm<HID_, EMB_, true><<<MTILES, dim3(16, 16)>>>(
        nullptr, edge_feat, node_emb, W2, src, dst);
    k_zn<<<(N_ + 3) / 4, 128>>>(node_emb, A2);
    k_logits<EMB_><<<(E_ + 3) / 4, 128>>>(A2 + EMB_, dst);
    k_exp<<<gE, 256>>>(dst);
    k_coef<<<gE, 256>>>(dst);
    k_agg<EMB_><<<(E_ * EMB_) / 256, 256>>>(dst);
    k_final<EMB_, false><<<(N_ + 15) / 16, 256>>>(node_emb, L2, b2, out);
}